// round 3
// baseline (speedup 1.0000x reference)
#include <cuda_runtime.h>

#define NQ 8192
#define MK 8192
#define BB 16
#define CC 512
#define LL 64
#define HH 8
#define DD 64

typedef unsigned long long u64;

__device__ float g_q[NQ * CC];
__device__ float g_k[MK * CC];
__device__ float g_v[MK * CC];
__device__ float g_attn[NQ * CC];
__device__ float g_aux_scratch[NQ * LL];
__device__ int   g_key_start[BB];

#define FMA2(d, a, b, c) \
    asm("fma.rn.f32x2 %0, %1, %2, %3;" : "=l"(d) : "l"(a), "l"(b), "l"(c))

// ---------------------------------------------------------------------------
__global__ void key_start_kernel(const int* __restrict__ key_batch_cnt) {
    if (threadIdx.x == 0) {
        int s = 0;
        for (int b = 0; b < BB; b++) { g_key_start[b] = s; s += key_batch_cnt[b]; }
    }
}

// ---------------------------------------------------------------------------
// Packed-f32x2 SGEMM (NT): C[r,c] = alpha * (sum_k A[r,k]*Bw[c,k] + bias[c])
// BM=BN=128, BK=16, 256 threads, 8x8 micro-tile computed as 8x4 float2 pairs.
// A is stored DUPLICATED in smem so a-broadcast pairs load directly as 64-bit.
// ---------------------------------------------------------------------------
__device__ __forceinline__ void sgemm_body(
    const float* __restrict__ A, const float* __restrict__ Bw,
    const float* __restrict__ bias, float* __restrict__ C,
    int K, int N, int row0, int col0, float alpha)
{
    __shared__ __align__(16) float As[2][16][256];   // duplicated pairs
    __shared__ __align__(16) float Bs[2][16][128];

    const int tid = threadIdx.x;
    const int tx  = tid & 15;
    const int ty  = tid >> 4;
    const int lr  = tid >> 2;          // 0..63
    const int lk  = (tid & 3) << 2;    // 0,4,8,12

    const float* Arow0 = &A[(size_t)(row0 + lr) * K + lk];
    const float* Arow1 = &A[(size_t)(row0 + lr + 64) * K + lk];
    const float* Brow0 = &Bw[(size_t)(col0 + lr) * K + lk];
    const float* Brow1 = &Bw[(size_t)(col0 + lr + 64) * K + lk];

    u64 acc2[8][4];
#pragma unroll
    for (int i = 0; i < 8; i++)
#pragma unroll
        for (int j = 0; j < 4; j++) acc2[i][j] = 0ull;

#define STORE_TILE(nb, a0, a1, b0, b1)                                          \
    do {                                                                        \
        *reinterpret_cast<float2*>(&As[nb][lk+0][2*lr])      = make_float2(a0.x, a0.x); \
        *reinterpret_cast<float2*>(&As[nb][lk+1][2*lr])      = make_float2(a0.y, a0.y); \
        *reinterpret_cast<float2*>(&As[nb][lk+2][2*lr])      = make_float2(a0.z, a0.z); \
        *reinterpret_cast<float2*>(&As[nb][lk+3][2*lr])      = make_float2(a0.w, a0.w); \
        *reinterpret_cast<float2*>(&As[nb][lk+0][2*(lr+64)]) = make_float2(a1.x, a1.x); \
        *reinterpret_cast<float2*>(&As[nb][lk+1][2*(lr+64)]) = make_float2(a1.y, a1.y); \
        *reinterpret_cast<float2*>(&As[nb][lk+2][2*(lr+64)]) = make_float2(a1.z, a1.z); \
        *reinterpret_cast<float2*>(&As[nb][lk+3][2*(lr+64)]) = make_float2(a1.w, a1.w); \
        Bs[nb][lk+0][lr] = b0.x; Bs[nb][lk+1][lr] = b0.y;                       \
        Bs[nb][lk+2][lr] = b0.z; Bs[nb][lk+3][lr] = b0.w;                       \
        Bs[nb][lk+0][lr+64] = b1.x; Bs[nb][lk+1][lr+64] = b1.y;                 \
        Bs[nb][lk+2][lr+64] = b1.z; Bs[nb][lk+3][lr+64] = b1.w;                 \
    } while (0)

#define COMPUTE_TILE(buf)                                                        \
    do {                                                                         \
        _Pragma("unroll")                                                        \
        for (int k = 0; k < 16; k++) {                                           \
            const ulonglong2* ap = reinterpret_cast<const ulonglong2*>(&As[buf][k][ty * 16]); \
            const ulonglong2* bp = reinterpret_cast<const ulonglong2*>(&Bs[buf][k][tx * 8]);  \
            ulonglong2 av0 = ap[0], av1 = ap[1], av2 = ap[2], av3 = ap[3];       \
            ulonglong2 bv0 = bp[0], bv1 = bp[1];                                 \
            u64 a2[8] = {av0.x, av0.y, av1.x, av1.y, av2.x, av2.y, av3.x, av3.y};\
            u64 b2[4] = {bv0.x, bv0.y, bv1.x, bv1.y};                            \
            _Pragma("unroll")                                                    \
            for (int i = 0; i < 8; i++) {                                        \
                FMA2(acc2[i][0], a2[i], b2[0], acc2[i][0]);                      \
                FMA2(acc2[i][1], a2[i], b2[1], acc2[i][1]);                      \
                FMA2(acc2[i][2], a2[i], b2[2], acc2[i][2]);                      \
                FMA2(acc2[i][3], a2[i], b2[3], acc2[i][3]);                      \
            }                                                                    \
        }                                                                        \
    } while (0)

    // prologue: tile 0 -> buffer 0
    {
        float4 a0 = *reinterpret_cast<const float4*>(Arow0);
        float4 a1 = *reinterpret_cast<const float4*>(Arow1);
        float4 b0 = *reinterpret_cast<const float4*>(Brow0);
        float4 b1 = *reinterpret_cast<const float4*>(Brow1);
        STORE_TILE(0, a0, a1, b0, b1);
    }
    __syncthreads();

    int buf = 0;
    for (int k0 = 16; k0 < K; k0 += 16) {
        float4 a0 = *reinterpret_cast<const float4*>(Arow0 + k0);
        float4 a1 = *reinterpret_cast<const float4*>(Arow1 + k0);
        float4 b0 = *reinterpret_cast<const float4*>(Brow0 + k0);
        float4 b1 = *reinterpret_cast<const float4*>(Brow1 + k0);

        COMPUTE_TILE(buf);

        int nb = buf ^ 1;
        STORE_TILE(nb, a0, a1, b0, b1);
        __syncthreads();
        buf = nb;
    }

    COMPUTE_TILE(buf);

    float breg[8];
#pragma unroll
    for (int j = 0; j < 8; j++) breg[j] = bias[col0 + tx * 8 + j];

#pragma unroll
    for (int i = 0; i < 8; i++) {
        size_t r = (size_t)(row0 + ty * 8 + i);
        float4 o0, o1;
        float2 p0 = *reinterpret_cast<float2*>(&acc2[i][0]);
        float2 p1 = *reinterpret_cast<float2*>(&acc2[i][1]);
        float2 p2 = *reinterpret_cast<float2*>(&acc2[i][2]);
        float2 p3 = *reinterpret_cast<float2*>(&acc2[i][3]);
        o0.x = alpha * (p0.x + breg[0]);
        o0.y = alpha * (p0.y + breg[1]);
        o0.z = alpha * (p1.x + breg[2]);
        o0.w = alpha * (p1.y + breg[3]);
        o1.x = alpha * (p2.x + breg[4]);
        o1.y = alpha * (p2.y + breg[5]);
        o1.z = alpha * (p3.x + breg[6]);
        o1.w = alpha * (p3.y + breg[7]);
        *reinterpret_cast<float4*>(&C[r * N + col0 + tx * 8])     = o0;
        *reinterpret_cast<float4*>(&C[r * N + col0 + tx * 8 + 4]) = o1;
    }
#undef STORE_TILE
#undef COMPUTE_TILE
}

__global__ void __launch_bounds__(256, 2) proj3_kernel(
    const float* __restrict__ query, const float* __restrict__ key,
    const float* __restrict__ value, const float* __restrict__ Win,
    const float* __restrict__ bin)
{
    const int z = blockIdx.z;
    const float* A = (z == 0) ? query : (z == 1) ? key : value;
    float* Cout = (z == 0) ? g_q : (z == 1) ? g_k : g_v;
    const float alpha = (z == 0) ? 0.125f : 1.0f;
    sgemm_body(A, Win + (size_t)z * CC * CC, bin + z * CC, Cout,
               CC, CC, blockIdx.y * 128, blockIdx.x * 128, alpha);
}

__global__ void __launch_bounds__(256, 2) outproj_kernel(
    const float* __restrict__ Wout, const float* __restrict__ bout,
    float* __restrict__ out)
{
    sgemm_body(g_attn, Wout, bout, out, CC, CC,
               blockIdx.y * 128, blockIdx.x * 128, 1.0f);
}

// ---------------------------------------------------------------------------
// Gather attention, one block (4 warps) per query.
// ---------------------------------------------------------------------------
__global__ void __launch_bounds__(128) attn_kernel(
    const int* __restrict__ index_pair,
    const int* __restrict__ index_pair_batch,
    float* __restrict__ aux_out)
{
    __shared__ __align__(16) float sq[CC];
    __shared__ float sw[LL * HH];
    __shared__ int   sg[LL];

    const int n = blockIdx.x;
    const int t = threadIdx.x;
    const int warp = t >> 5;
    const int lane = t & 31;

    *reinterpret_cast<float4*>(&sq[t * 4]) =
        *reinterpret_cast<const float4*>(&g_q[(size_t)n * CC + t * 4]);

    if (t < LL) {
        int raw = index_pair[n * LL + t];
        int b   = index_pair_batch[n];
        sg[t] = (raw >= 0) ? (raw + g_key_start[b]) : -1;
    }
    __syncthreads();

    const float4* sq4 = reinterpret_cast<const float4*>(sq);
#pragma unroll 1
    for (int li = 0; li < 16; li++) {
        int l = warp * 16 + li;
        int g = sg[l];
        if (g < 0) {
            if (lane < 8) sw[l * 8 + lane] = -1000.0f;
            continue;
        }
        const float4* kr = reinterpret_cast<const float4*>(&g_k[(size_t)g * CC]);
#pragma unroll
        for (int p = 0; p < 4; p++) {
            float4 kv = kr[p * 32 + lane];
            float4 q4 = sq4[p * 32 + lane];
            float s = kv.x * q4.x + kv.y * q4.y + kv.z * q4.z + kv.w * q4.w;
            s += __shfl_xor_sync(0xffffffffu, s, 1);
            s += __shfl_xor_sync(0xffffffffu, s, 2);
            s += __shfl_xor_sync(0xffffffffu, s, 4);
            s += __shfl_xor_sync(0xffffffffu, s, 8);
            if ((lane & 15) == 0)
                sw[l * 8 + 2 * p + (lane >> 4)] = s;
        }
    }
    __syncthreads();

    {
        int h = t >> 4, j = t & 15;
        float vals[4];
        float m = -1e30f;
#pragma unroll
        for (int i = 0; i < 4; i++) {
            vals[i] = sw[(j + 16 * i) * 8 + h];
            m = fmaxf(m, vals[i]);
        }
#pragma unroll
        for (int off = 8; off; off >>= 1)
            m = fmaxf(m, __shfl_xor_sync(0xffffffffu, m, off, 16));
        float s = 0.0f;
#pragma unroll
        for (int i = 0; i < 4; i++) { vals[i] = expf(vals[i] - m); s += vals[i]; }
#pragma unroll
        for (int off = 8; off; off >>= 1)
            s += __shfl_xor_sync(0xffffffffu, s, off, 16);
        float inv = 1.0f / s;
#pragma unroll
        for (int i = 0; i < 4; i++)
            sw[(j + 16 * i) * 8 + h] = vals[i] * inv;
    }
    __syncthreads();

    if (t < LL) {
        float s = 0.0f;
#pragma unroll
        for (int h = 0; h < 8; h++) s += sw[t * 8 + h];
        aux_out[(size_t)n * LL + t] = s * 0.125f;
    }

    {
        int h  = t >> 4;
        int d4 = t & 15;
        float4 acc = make_float4(0.f, 0.f, 0.f, 0.f);
        size_t coloff = (size_t)(h * DD + d4 * 4);
#pragma unroll 4
        for (int l = 0; l < LL; l++) {
            int g = sg[l];
            int gg = (g >= 0) ? g : 0;
            float w = sw[l * 8 + h];
            float4 v4 = *reinterpret_cast<const float4*>(&g_v[(size_t)gg * CC + coloff]);
            acc.x = fmaf(w, v4.x, acc.x);
            acc.y = fmaf(w, v4.y, acc.y);
            acc.z = fmaf(w, v4.z, acc.z);
            acc.w = fmaf(w, v4.w, acc.w);
        }
        *reinterpret_cast<float4*>(&g_attn[(size_t)n * CC + coloff]) = acc;
    }
}

// ---------------------------------------------------------------------------
extern "C" void kernel_launch(void* const* d_in, const int* in_sizes, int n_in,
                              void* d_out, int out_size) {
    const float* query  = (const float*)d_in[0];
    const float* key    = (const float*)d_in[1];
    const float* value  = (const float*)d_in[2];
    const float* Win    = (const float*)d_in[3];
    const float* bin    = (const float*)d_in[4];
    const float* Wout   = (const float*)d_in[5];
    const float* bout   = (const float*)d_in[6];
    const int*   index_pair       = (const int*)d_in[7];
    const int*   key_batch_cnt    = (const int*)d_in[9];
    const int*   index_pair_batch = (const int*)d_in[10];
    float* out = (float*)d_out;

    float* auxs;
    cudaGetSymbolAddress((void**)&auxs, g_aux_scratch);
    float* aux_out = (out_size >= NQ * CC + NQ * LL) ? (out + (size_t)NQ * CC) : auxs;

    key_start_kernel<<<1, 32>>>(key_batch_cnt);

    dim3 gproj(CC / 128, NQ / 128, 3);
    proj3_kernel<<<gproj, 256>>>(query, key, value, Win, bin);

    attn_kernel<<<NQ, 128>>>(index_pair, index_pair_batch, aux_out);

    dim3 gout(CC / 128, NQ / 128);
    outproj_kernel<<<gout, 256>>>(Wout, bout, out);
}

// round 5
// speedup vs baseline: 1.9116x; 1.9116x over previous
#include <cuda_runtime.h>
#include <cstdint>

#define NQ 8192
#define MK 8192
#define BB 16
#define CC 512
#define LL 64
#define HH 8
#define DD 64

// fp32 intermediates consumed by the attention kernel
__device__ float g_q[NQ * CC];
__device__ float g_k[MK * CC];
__device__ float g_v[MK * CC];
__device__ float g_aux_scratch[NQ * LL];
__device__ int   g_key_start[BB];

// bf16 split operands (hi/lo), packed 2 elements per uint32
__device__ uint32_t g_bQh[NQ * CC / 2], g_bQl[NQ * CC / 2];
__device__ uint32_t g_bKh[MK * CC / 2], g_bKl[MK * CC / 2];
__device__ uint32_t g_bVh[MK * CC / 2], g_bVl[MK * CC / 2];
__device__ uint32_t g_bWih[3 * CC * CC / 2], g_bWil[3 * CC * CC / 2];
__device__ uint32_t g_bWoh[CC * CC / 2],     g_bWol[CC * CC / 2];
__device__ uint32_t g_bAh[NQ * CC / 2],      g_bAl[NQ * CC / 2];

// ---------------------------------------------------------------------------
static __device__ __forceinline__ uint32_t smem_u32(const void* p) {
    uint32_t a;
    asm("{ .reg .u64 t; cvta.to.shared.u64 t, %1; cvt.u32.u64 %0, t; }" : "=r"(a) : "l"(p));
    return a;
}
static __device__ __forceinline__ uint32_t packbf(float f0, float f1) {
    uint32_t r;  // low 16 = bf16(f0), high 16 = bf16(f1)
    asm("cvt.rn.bf16x2.f32 %0, %1, %2;" : "=r"(r) : "f"(f1), "f"(f0));
    return r;
}
static __device__ __forceinline__ float bflo(uint32_t r) { return __uint_as_float(r << 16); }
static __device__ __forceinline__ float bfhi(uint32_t r) { return __uint_as_float(r & 0xffff0000u); }
static __device__ __forceinline__ uint32_t lds32(uint32_t a) {
    uint32_t v; asm volatile("ld.shared.b32 %0, [%1];" : "=r"(v) : "r"(a)); return v;
}
static __device__ __forceinline__ void cpa16(uint32_t dst, const void* src) {
    asm volatile("cp.async.cg.shared.global [%0], [%1], 16;" :: "r"(dst), "l"(src) : "memory");
}
#define CP_COMMIT asm volatile("cp.async.commit_group;" ::: "memory")
#define CP_WAIT1  asm volatile("cp.async.wait_group 1;" ::: "memory")
#define CP_WAIT0  asm volatile("cp.async.wait_group 0;" ::: "memory")

#define MMA_BF16(c, a0, a1, a2, a3, b0, b1)                                   \
    asm volatile(                                                             \
        "mma.sync.aligned.m16n8k16.row.col.f32.bf16.bf16.f32 "                \
        "{%0,%1,%2,%3},{%4,%5,%6,%7},{%8,%9},{%0,%1,%2,%3};"                  \
        : "+f"((c)[0]), "+f"((c)[1]), "+f"((c)[2]), "+f"((c)[3])              \
        : "r"(a0), "r"(a1), "r"(a2), "r"(a3), "r"(b0), "r"(b1))

// ---------------------------------------------------------------------------
__global__ void key_start_kernel(const int* __restrict__ key_batch_cnt) {
    if (threadIdx.x == 0) {
        int s = 0;
        for (int b = 0; b < BB; b++) { g_key_start[b] = s; s += key_batch_cnt[b]; }
    }
}

// fp32 -> (bf16 hi, bf16 lo) split, vectorized 4 floats/thread
__global__ void __launch_bounds__(256) cvt_split_kernel(
    const float4* __restrict__ src, uint2* __restrict__ hi, uint2* __restrict__ lo, int n4)
{
    int i = blockIdx.x * blockDim.x + threadIdx.x;
    if (i >= n4) return;
    float4 f = src[i];
    uint32_t h0 = packbf(f.x, f.y);
    uint32_t h1 = packbf(f.z, f.w);
    uint32_t l0 = packbf(f.x - bflo(h0), f.y - bfhi(h0));
    uint32_t l1 = packbf(f.z - bflo(h1), f.w - bfhi(h1));
    hi[i] = make_uint2(h0, h1);
    lo[i] = make_uint2(l0, l1);
}

// ===========================================================================
// Split-bf16 HMMA GEMM: C[r,c] = alpha*(sum_k A[r,k]*B[c,k] + bias[c])
// 128x128 CTA tile, 8 warps (2x4) of 64x32, m16n8k16, BK=32, cp.async 2-stage.
// Smem rows padded to 80B (40 bf16) -> conflict-free fragment LDS.
// ===========================================================================
#define SROWB 80                    // padded row bytes
#define TILE_B (128 * SROWB)        // 10240 B per matrix tile
#define STAGE_B (4 * TILE_B)        // Ah, Al, Bh, Bl
#define DSMEM_SIZE (2 * STAGE_B)    // 81920 B

__device__ __forceinline__ void gemm_bf16_body(
    const uint32_t* __restrict__ Ah, const uint32_t* __restrict__ Al,
    const uint32_t* __restrict__ Bh, const uint32_t* __restrict__ Bl,
    const float* __restrict__ bias, float* __restrict__ Cout, float alpha)
{
    extern __shared__ char dsm[];
    const uint32_t sbase = smem_u32(dsm);

    const int t = threadIdx.x;
    const int lane = t & 31, warp = t >> 5;
    const int g = lane >> 2, tig = lane & 3;
    const int warpM = warp & 1, warpN = warp >> 1;
    const int row0 = blockIdx.y * 128, col0 = blockIdx.x * 128;

    // copy role: 2 threads per tile row
    const int crow = t >> 1, chalf = t & 1;
    const uint32_t dstoff = (uint32_t)(crow * SROWB + chalf * 32);
    const size_t srcAbase = (size_t)(row0 + crow) * (CC / 2) + chalf * 8;
    const size_t srcBbase = (size_t)(col0 + crow) * (CC / 2) + chalf * 8;

    float acc[4][4][4];
#pragma unroll
    for (int m = 0; m < 4; m++)
#pragma unroll
        for (int n = 0; n < 4; n++)
#pragma unroll
            for (int j = 0; j < 4; j++) acc[m][n][j] = 0.0f;

#define ISSUE(kt, buf)                                                         \
    do {                                                                       \
        uint32_t sb = sbase + (buf) * STAGE_B;                                 \
        size_t ksrc = (size_t)(kt) * 16;                                       \
        cpa16(sb + dstoff,                  Ah + srcAbase + ksrc);             \
        cpa16(sb + dstoff + 16,             Ah + srcAbase + ksrc + 4);         \
        cpa16(sb + TILE_B + dstoff,         Al + srcAbase + ksrc);             \
        cpa16(sb + TILE_B + dstoff + 16,    Al + srcAbase + ksrc + 4);         \
        cpa16(sb + 2*TILE_B + dstoff,       Bh + srcBbase + ksrc);             \
        cpa16(sb + 2*TILE_B + dstoff + 16,  Bh + srcBbase + ksrc + 4);         \
        cpa16(sb + 3*TILE_B + dstoff,       Bl + srcBbase + ksrc);             \
        cpa16(sb + 3*TILE_B + dstoff + 16,  Bl + srcBbase + ksrc + 4);         \
    } while (0)

    const int NT = CC / 32;   // 16 k-stages
    ISSUE(0, 0);
    CP_COMMIT;

    for (int kt = 0; kt < NT; kt++) {
        if (kt + 1 < NT) {
            ISSUE(kt + 1, (kt + 1) & 1);
            CP_COMMIT;
            CP_WAIT1;
        } else {
            CP_WAIT0;
        }
        __syncthreads();

        const uint32_t ab = sbase + (kt & 1) * STAGE_B;
#pragma unroll
        for (int sub = 0; sub < 2; sub++) {
            const uint32_t koff = sub * 32;
            uint32_t ah[4][4], al[4][4];
#pragma unroll
            for (int m = 0; m < 4; m++) {
                uint32_t ro = ab + (uint32_t)((warpM * 64 + m * 16 + g) * SROWB) + koff + tig * 4;
                ah[m][0] = lds32(ro);
                ah[m][1] = lds32(ro + 8 * SROWB);
                ah[m][2] = lds32(ro + 16);
                ah[m][3] = lds32(ro + 8 * SROWB + 16);
                al[m][0] = lds32(ro + TILE_B);
                al[m][1] = lds32(ro + TILE_B + 8 * SROWB);
                al[m][2] = lds32(ro + TILE_B + 16);
                al[m][3] = lds32(ro + TILE_B + 8 * SROWB + 16);
            }
#pragma unroll
            for (int n = 0; n < 4; n++) {
                uint32_t bo = ab + 2 * TILE_B +
                    (uint32_t)((warpN * 32 + n * 8 + g) * SROWB) + koff + tig * 4;
                uint32_t bh0 = lds32(bo), bh1 = lds32(bo + 16);
                uint32_t bl0 = lds32(bo + TILE_B), bl1 = lds32(bo + TILE_B + 16);
#pragma unroll
                for (int m = 0; m < 4; m++) {
                    MMA_BF16(acc[m][n], ah[m][0], ah[m][1], ah[m][2], ah[m][3], bh0, bh1);
                    MMA_BF16(acc[m][n], ah[m][0], ah[m][1], ah[m][2], ah[m][3], bl0, bl1);
                    MMA_BF16(acc[m][n], al[m][0], al[m][1], al[m][2], al[m][3], bh0, bh1);
                }
            }
        }
        __syncthreads();
    }
#undef ISSUE

    // epilogue
#pragma unroll
    for (int m = 0; m < 4; m++) {
        int rg = row0 + warpM * 64 + m * 16 + g;
#pragma unroll
        for (int n = 0; n < 4; n++) {
            int col = col0 + warpN * 32 + n * 8 + tig * 2;
            float b0 = __ldg(&bias[col]), b1 = __ldg(&bias[col + 1]);
            float2 o;
            o.x = alpha * (acc[m][n][0] + b0);
            o.y = alpha * (acc[m][n][1] + b1);
            *reinterpret_cast<float2*>(&Cout[(size_t)rg * CC + col]) = o;
            o.x = alpha * (acc[m][n][2] + b0);
            o.y = alpha * (acc[m][n][3] + b1);
            *reinterpret_cast<float2*>(&Cout[(size_t)(rg + 8) * CC + col]) = o;
        }
    }
}

__global__ void __launch_bounds__(256, 2) proj3_mma(const float* __restrict__ bin) {
    const int z = blockIdx.z;
    const uint32_t* Ahz = (z == 0) ? g_bQh : (z == 1) ? g_bKh : g_bVh;
    const uint32_t* Alz = (z == 0) ? g_bQl : (z == 1) ? g_bKl : g_bVl;
    float* Cz = (z == 0) ? g_q : (z == 1) ? g_k : g_v;
    const float alpha = (z == 0) ? 0.125f : 1.0f;
    gemm_bf16_body(Ahz, Alz,
                   g_bWih + (size_t)z * (CC * CC / 2),
                   g_bWil + (size_t)z * (CC * CC / 2),
                   bin + z * CC, Cz, alpha);
}

__global__ void __launch_bounds__(256, 2) outproj_mma(
    const float* __restrict__ bout, float* __restrict__ out) {
    gemm_bf16_body(g_bAh, g_bAl, g_bWoh, g_bWol, bout, out, 1.0f);
}

// ---------------------------------------------------------------------------
// Gather attention: one block (4 warps) per query. Output written as split
// bf16 (hi/lo) feeding the HMMA output projection.
// ---------------------------------------------------------------------------
__global__ void __launch_bounds__(128) attn_kernel(
    const int* __restrict__ index_pair,
    const int* __restrict__ index_pair_batch,
    float* __restrict__ aux_out)
{
    __shared__ __align__(16) float sq[CC];
    __shared__ float sw[LL * HH];
    __shared__ int   sg[LL];

    const int n = blockIdx.x;
    const int t = threadIdx.x;
    const int warp = t >> 5;
    const int lane = t & 31;

    *reinterpret_cast<float4*>(&sq[t * 4]) =
        *reinterpret_cast<const float4*>(&g_q[(size_t)n * CC + t * 4]);

    if (t < LL) {
        int raw = index_pair[n * LL + t];
        int b   = index_pair_batch[n];
        sg[t] = (raw >= 0) ? (raw + g_key_start[b]) : -1;
    }
    __syncthreads();

    const float4* sq4 = reinterpret_cast<const float4*>(sq);
#pragma unroll 1
    for (int li = 0; li < 16; li++) {
        int l = warp * 16 + li;
        int g = sg[l];
        if (g < 0) {
            if (lane < 8) sw[l * 8 + lane] = -1000.0f;
            continue;
        }
        const float4* kr = reinterpret_cast<const float4*>(&g_k[(size_t)g * CC]);
#pragma unroll
        for (int p = 0; p < 4; p++) {
            float4 kv = kr[p * 32 + lane];
            float4 q4 = sq4[p * 32 + lane];
            float s = kv.x * q4.x + kv.y * q4.y + kv.z * q4.z + kv.w * q4.w;
            s += __shfl_xor_sync(0xffffffffu, s, 1);
            s += __shfl_xor_sync(0xffffffffu, s, 2);
            s += __shfl_xor_sync(0xffffffffu, s, 4);
            s += __shfl_xor_sync(0xffffffffu, s, 8);
            if ((lane & 15) == 0)
                sw[l * 8 + 2 * p + (lane >> 4)] = s;
        }
    }
    __syncthreads();

    {
        int h = t >> 4, j = t & 15;
        float vals[4];
        float m = -1e30f;
#pragma unroll
        for (int i = 0; i < 4; i++) {
            vals[i] = sw[(j + 16 * i) * 8 + h];
            m = fmaxf(m, vals[i]);
        }
#pragma unroll
        for (int off = 8; off; off >>= 1)
            m = fmaxf(m, __shfl_xor_sync(0xffffffffu, m, off, 16));
        float s = 0.0f;
#pragma unroll
        for (int i = 0; i < 4; i++) { vals[i] = expf(vals[i] - m); s += vals[i]; }
#pragma unroll
        for (int off = 8; off; off >>= 1)
            s += __shfl_xor_sync(0xffffffffu, s, off, 16);
        float inv = 1.0f / s;
#pragma unroll
        for (int i = 0; i < 4; i++)
            sw[(j + 16 * i) * 8 + h] = vals[i] * inv;
    }
    __syncthreads();

    if (t < LL) {
        float s = 0.0f;
#pragma unroll
        for (int h = 0; h < 8; h++) s += sw[t * 8 + h];
        aux_out[(size_t)n * LL + t] = s * 0.125f;
    }

    {
        int h  = t >> 4;
        int d4 = t & 15;
        float4 acc = make_float4(0.f, 0.f, 0.f, 0.f);
        size_t coloff = (size_t)(h * DD + d4 * 4);
#pragma unroll 4
        for (int l = 0; l < LL; l++) {
            int g = sg[l];
            int gg = (g >= 0) ? g : 0;
            float wgt = sw[l * 8 + h];
            float4 v4 = *reinterpret_cast<const float4*>(&g_v[(size_t)gg * CC + coloff]);
            acc.x = fmaf(wgt, v4.x, acc.x);
            acc.y = fmaf(wgt, v4.y, acc.y);
            acc.z = fmaf(wgt, v4.z, acc.z);
            acc.w = fmaf(wgt, v4.w, acc.w);
        }
        uint32_t h0 = packbf(acc.x, acc.y);
        uint32_t h1 = packbf(acc.z, acc.w);
        uint32_t l0 = packbf(acc.x - bflo(h0), acc.y - bfhi(h0));
        uint32_t l1 = packbf(acc.z - bflo(h1), acc.w - bfhi(h1));
        size_t o2 = ((size_t)n * CC + coloff) >> 1;
        *reinterpret_cast<uint2*>(&g_bAh[o2]) = make_uint2(h0, h1);
        *reinterpret_cast<uint2*>(&g_bAl[o2]) = make_uint2(l0, l1);
    }
}

// ---------------------------------------------------------------------------
extern "C" void kernel_launch(void* const* d_in, const int* in_sizes, int n_in,
                              void* d_out, int out_size) {
    const float* query  = (const float*)d_in[0];
    const float* key    = (const float*)d_in[1];
    const float* value  = (const float*)d_in[2];
    const float* Win    = (const float*)d_in[3];
    const float* bin    = (const float*)d_in[4];
    const float* Wout   = (const float*)d_in[5];
    const float* bout   = (const float*)d_in[6];
    const int*   index_pair       = (const int*)d_in[7];
    const int*   key_batch_cnt    = (const int*)d_in[9];
    const int*   index_pair_batch = (const int*)d_in[10];
    float* out = (float*)d_out;

    float* auxs;
    cudaGetSymbolAddress((void**)&auxs, g_aux_scratch);
    float* aux_out = (out_size >= NQ * CC + NQ * LL) ? (out + (size_t)NQ * CC) : auxs;

    uint32_t *bQh, *bQl, *bKh, *bKl, *bVh, *bVl, *bWih, *bWil, *bWoh, *bWol;
    cudaGetSymbolAddress((void**)&bQh, g_bQh);  cudaGetSymbolAddress((void**)&bQl, g_bQl);
    cudaGetSymbolAddress((void**)&bKh, g_bKh);  cudaGetSymbolAddress((void**)&bKl, g_bKl);
    cudaGetSymbolAddress((void**)&bVh, g_bVh);  cudaGetSymbolAddress((void**)&bVl, g_bVl);
    cudaGetSymbolAddress((void**)&bWih, g_bWih); cudaGetSymbolAddress((void**)&bWil, g_bWil);
    cudaGetSymbolAddress((void**)&bWoh, g_bWoh); cudaGetSymbolAddress((void**)&bWol, g_bWol);

    cudaFuncSetAttribute(proj3_mma,   cudaFuncAttributeMaxDynamicSharedMemorySize, DSMEM_SIZE);
    cudaFuncSetAttribute(outproj_mma, cudaFuncAttributeMaxDynamicSharedMemorySize, DSMEM_SIZE);

    key_start_kernel<<<1, 32>>>(key_batch_cnt);

    // fp32 -> split-bf16 conversions
    cvt_split_kernel<<<NQ * CC / 4 / 256, 256>>>(
        (const float4*)query, (uint2*)bQh, (uint2*)bQl, NQ * CC / 4);
    cvt_split_kernel<<<MK * CC / 4 / 256, 256>>>(
        (const float4*)key, (uint2*)bKh, (uint2*)bKl, MK * CC / 4);
    cvt_split_kernel<<<MK * CC / 4 / 256, 256>>>(
        (const float4*)value, (uint2*)bVh, (uint2*)bVl, MK * CC / 4);
    cvt_split_kernel<<<3 * CC * CC / 4 / 256, 256>>>(
        (const float4*)Win, (uint2*)bWih, (uint2*)bWil, 3 * CC * CC / 4);
    cvt_split_kernel<<<CC * CC / 4 / 256, 256>>>(
        (const float4*)Wout, (uint2*)bWoh, (uint2*)bWol, CC * CC / 4);

    dim3 gproj(CC / 128, NQ / 128, 3);
    proj3_mma<<<gproj, 256, DSMEM_SIZE>>>(bin);

    attn_kernel<<<NQ, 128>>>(index_pair, index_pair_batch, aux_out);

    dim3 gout(CC / 128, NQ / 128);
    outproj_mma<<<gout, 256, DSMEM_SIZE>>>(bout, out);
}

// round 6
// speedup vs baseline: 1.9319x; 1.0106x over previous
#include <cuda_runtime.h>
#include <cstdint>

#define NQ 8192
#define MK 8192
#define BB 16
#define CC 512
#define LL 64
#define HH 8
#define DD 64

// fp32 intermediates consumed by the attention kernel
__device__ float g_q[NQ * CC];
__device__ float g_k[MK * CC];
__device__ float g_v[MK * CC];
__device__ float g_aux_scratch[NQ * LL];
__device__ int   g_key_start[BB];

// bf16 split operands (hi/lo), packed 2 elements per uint32
__device__ uint32_t g_bQh[NQ * CC / 2], g_bQl[NQ * CC / 2];
__device__ uint32_t g_bKh[MK * CC / 2], g_bKl[MK * CC / 2];
__device__ uint32_t g_bVh[MK * CC / 2], g_bVl[MK * CC / 2];
__device__ uint32_t g_bWih[3 * CC * CC / 2], g_bWil[3 * CC * CC / 2];
__device__ uint32_t g_bWoh[CC * CC / 2],     g_bWol[CC * CC / 2];
__device__ uint32_t g_bAh[NQ * CC / 2],      g_bAl[NQ * CC / 2];

// ---------------------------------------------------------------------------
static __device__ __forceinline__ uint32_t smem_u32(const void* p) {
    uint32_t a;
    asm("{ .reg .u64 t; cvta.to.shared.u64 t, %1; cvt.u32.u64 %0, t; }" : "=r"(a) : "l"(p));
    return a;
}
static __device__ __forceinline__ uint32_t packbf(float f0, float f1) {
    uint32_t r;  // low 16 = bf16(f0), high 16 = bf16(f1)
    asm("cvt.rn.bf16x2.f32 %0, %1, %2;" : "=r"(r) : "f"(f1), "f"(f0));
    return r;
}
static __device__ __forceinline__ float bflo(uint32_t r) { return __uint_as_float(r << 16); }
static __device__ __forceinline__ float bfhi(uint32_t r) { return __uint_as_float(r & 0xffff0000u); }
static __device__ __forceinline__ uint32_t lds32(uint32_t a) {
    uint32_t v; asm volatile("ld.shared.b32 %0, [%1];" : "=r"(v) : "r"(a)); return v;
}
static __device__ __forceinline__ void cpa16(uint32_t dst, const void* src) {
    asm volatile("cp.async.cg.shared.global [%0], [%1], 16;" :: "r"(dst), "l"(src) : "memory");
}
#define CP_COMMIT asm volatile("cp.async.commit_group;" ::: "memory")
#define CP_WAIT1  asm volatile("cp.async.wait_group 1;" ::: "memory")
#define CP_WAIT0  asm volatile("cp.async.wait_group 0;" ::: "memory")

#define MMA_BF16(c, a0, a1, a2, a3, b0, b1)                                   \
    asm volatile(                                                             \
        "mma.sync.aligned.m16n8k16.row.col.f32.bf16.bf16.f32 "                \
        "{%0,%1,%2,%3},{%4,%5,%6,%7},{%8,%9},{%0,%1,%2,%3};"                  \
        : "+f"((c)[0]), "+f"((c)[1]), "+f"((c)[2]), "+f"((c)[3])              \
        : "r"(a0), "r"(a1), "r"(a2), "r"(a3), "r"(b0), "r"(b1))

// ---------------------------------------------------------------------------
__global__ void key_start_kernel(const int* __restrict__ key_batch_cnt) {
    if (threadIdx.x == 0) {
        int s = 0;
        for (int b = 0; b < BB; b++) { g_key_start[b] = s; s += key_batch_cnt[b]; }
    }
}

// fp32 -> (bf16 hi, bf16 lo) split; blockIdx.y selects q/k/v
__global__ void __launch_bounds__(256) cvt3_kernel(
    const float4* __restrict__ q, const float4* __restrict__ k,
    const float4* __restrict__ v)
{
    const int z = blockIdx.y;
    const float4* src = (z == 0) ? q : (z == 1) ? k : v;
    uint2* hi = (uint2*)((z == 0) ? g_bQh : (z == 1) ? g_bKh : g_bVh);
    uint2* lo = (uint2*)((z == 0) ? g_bQl : (z == 1) ? g_bKl : g_bVl);
    int i = blockIdx.x * blockDim.x + threadIdx.x;
    float4 f = src[i];
    uint32_t h0 = packbf(f.x, f.y);
    uint32_t h1 = packbf(f.z, f.w);
    uint32_t l0 = packbf(f.x - bflo(h0), f.y - bfhi(h0));
    uint32_t l1 = packbf(f.z - bflo(h1), f.w - bfhi(h1));
    hi[i] = make_uint2(h0, h1);
    lo[i] = make_uint2(l0, l1);
}

__global__ void __launch_bounds__(256) cvt_split_kernel(
    const float4* __restrict__ src, uint2* __restrict__ hi, uint2* __restrict__ lo, int n4)
{
    int i = blockIdx.x * blockDim.x + threadIdx.x;
    if (i >= n4) return;
    float4 f = src[i];
    uint32_t h0 = packbf(f.x, f.y);
    uint32_t h1 = packbf(f.z, f.w);
    uint32_t l0 = packbf(f.x - bflo(h0), f.y - bfhi(h0));
    uint32_t l1 = packbf(f.z - bflo(h1), f.w - bfhi(h1));
    hi[i] = make_uint2(h0, h1);
    lo[i] = make_uint2(l0, l1);
}

// ===========================================================================
// Split-bf16 HMMA GEMM: C[r,c] = alpha*(sum_k A[r,k]*B[c,k] + bias[c])
// 128x128 CTA tile, 8 warps (2x4) of 64x32, m16n8k16, BK=32, cp.async 2-stage.
// Two-pass A-frag scheme keeps live registers ~105 (no spill at 128-reg cap).
// ===========================================================================
#define SROWB 80                    // padded row bytes
#define TILE_B (128 * SROWB)        // 10240 B per matrix tile
#define STAGE_B (4 * TILE_B)        // Ah, Al, Bh, Bl
#define DSMEM_SIZE (2 * STAGE_B)    // 81920 B

__device__ __forceinline__ void gemm_bf16_body(
    const uint32_t* __restrict__ Ah, const uint32_t* __restrict__ Al,
    const uint32_t* __restrict__ Bh, const uint32_t* __restrict__ Bl,
    const float* __restrict__ bias, float* __restrict__ Cout, float alpha)
{
    extern __shared__ char dsm[];
    const uint32_t sbase = smem_u32(dsm);

    const int t = threadIdx.x;
    const int lane = t & 31, warp = t >> 5;
    const int g = lane >> 2, tig = lane & 3;
    const int warpM = warp & 1, warpN = warp >> 1;
    const int row0 = blockIdx.y * 128, col0 = blockIdx.x * 128;

    // copy role: 2 threads per tile row
    const int crow = t >> 1, chalf = t & 1;
    const uint32_t dstoff = (uint32_t)(crow * SROWB + chalf * 32);
    const size_t srcAbase = (size_t)(row0 + crow) * (CC / 2) + chalf * 8;
    const size_t srcBbase = (size_t)(col0 + crow) * (CC / 2) + chalf * 8;

    float acc[4][4][4];
#pragma unroll
    for (int m = 0; m < 4; m++)
#pragma unroll
        for (int n = 0; n < 4; n++)
#pragma unroll
            for (int j = 0; j < 4; j++) acc[m][n][j] = 0.0f;

#define ISSUE(kt, buf)                                                         \
    do {                                                                       \
        uint32_t sb = sbase + (buf) * STAGE_B;                                 \
        size_t ksrc = (size_t)(kt) * 16;                                       \
        cpa16(sb + dstoff,                  Ah + srcAbase + ksrc);             \
        cpa16(sb + dstoff + 16,             Ah + srcAbase + ksrc + 4);         \
        cpa16(sb + TILE_B + dstoff,         Al + srcAbase + ksrc);             \
        cpa16(sb + TILE_B + dstoff + 16,    Al + srcAbase + ksrc + 4);         \
        cpa16(sb + 2*TILE_B + dstoff,       Bh + srcBbase + ksrc);             \
        cpa16(sb + 2*TILE_B + dstoff + 16,  Bh + srcBbase + ksrc + 4);         \
        cpa16(sb + 3*TILE_B + dstoff,       Bl + srcBbase + ksrc);             \
        cpa16(sb + 3*TILE_B + dstoff + 16,  Bl + srcBbase + ksrc + 4);         \
    } while (0)

    const int NT = CC / 32;   // 16 k-stages
    ISSUE(0, 0);
    CP_COMMIT;

    for (int kt = 0; kt < NT; kt++) {
        if (kt + 1 < NT) {
            ISSUE(kt + 1, (kt + 1) & 1);
            CP_COMMIT;
            CP_WAIT1;
        } else {
            CP_WAIT0;
        }
        __syncthreads();

        const uint32_t ab = sbase + (kt & 1) * STAGE_B;
#pragma unroll
        for (int sub = 0; sub < 2; sub++) {
            const uint32_t koff = sub * 32;
            uint32_t af[4][4];

            // ---- pass 1: A-hi frags; terms Ah*Bh and Ah*Bl ----
#pragma unroll
            for (int m = 0; m < 4; m++) {
                uint32_t ro = ab + (uint32_t)((warpM * 64 + m * 16 + g) * SROWB) + koff + tig * 4;
                af[m][0] = lds32(ro);
                af[m][1] = lds32(ro + 8 * SROWB);
                af[m][2] = lds32(ro + 16);
                af[m][3] = lds32(ro + 8 * SROWB + 16);
            }
#pragma unroll
            for (int n = 0; n < 4; n++) {
                uint32_t bo = ab + 2 * TILE_B +
                    (uint32_t)((warpN * 32 + n * 8 + g) * SROWB) + koff + tig * 4;
                uint32_t bh0 = lds32(bo), bh1 = lds32(bo + 16);
                uint32_t bl0 = lds32(bo + TILE_B), bl1 = lds32(bo + TILE_B + 16);
#pragma unroll
                for (int m = 0; m < 4; m++) {
                    MMA_BF16(acc[m][n], af[m][0], af[m][1], af[m][2], af[m][3], bh0, bh1);
                    MMA_BF16(acc[m][n], af[m][0], af[m][1], af[m][2], af[m][3], bl0, bl1);
                }
            }

            // ---- pass 2: A-lo frags (reuse registers); term Al*Bh ----
#pragma unroll
            for (int m = 0; m < 4; m++) {
                uint32_t ro = ab + TILE_B +
                    (uint32_t)((warpM * 64 + m * 16 + g) * SROWB) + koff + tig * 4;
                af[m][0] = lds32(ro);
                af[m][1] = lds32(ro + 8 * SROWB);
                af[m][2] = lds32(ro + 16);
                af[m][3] = lds32(ro + 8 * SROWB + 16);
            }
#pragma unroll
            for (int n = 0; n < 4; n++) {
                uint32_t bo = ab + 2 * TILE_B +
                    (uint32_t)((warpN * 32 + n * 8 + g) * SROWB) + koff + tig * 4;
                uint32_t bh0 = lds32(bo), bh1 = lds32(bo + 16);
#pragma unroll
                for (int m = 0; m < 4; m++)
                    MMA_BF16(acc[m][n], af[m][0], af[m][1], af[m][2], af[m][3], bh0, bh1);
            }
        }
        __syncthreads();
    }
#undef ISSUE

    // epilogue
#pragma unroll
    for (int m = 0; m < 4; m++) {
        int rg = row0 + warpM * 64 + m * 16 + g;
#pragma unroll
        for (int n = 0; n < 4; n++) {
            int col = col0 + warpN * 32 + n * 8 + tig * 2;
            float b0 = __ldg(&bias[col]), b1 = __ldg(&bias[col + 1]);
            float2 o;
            o.x = alpha * (acc[m][n][0] + b0);
            o.y = alpha * (acc[m][n][1] + b1);
            *reinterpret_cast<float2*>(&Cout[(size_t)rg * CC + col]) = o;
            o.x = alpha * (acc[m][n][2] + b0);
            o.y = alpha * (acc[m][n][3] + b1);
            *reinterpret_cast<float2*>(&Cout[(size_t)(rg + 8) * CC + col]) = o;
        }
    }
}

__global__ void __launch_bounds__(256, 2) proj3_mma(const float* __restrict__ bin) {
    const int z = blockIdx.z;
    const uint32_t* Ahz = (z == 0) ? g_bQh : (z == 1) ? g_bKh : g_bVh;
    const uint32_t* Alz = (z == 0) ? g_bQl : (z == 1) ? g_bKl : g_bVl;
    float* Cz = (z == 0) ? g_q : (z == 1) ? g_k : g_v;
    const float alpha = (z == 0) ? 0.125f : 1.0f;
    gemm_bf16_body(Ahz, Alz,
                   g_bWih + (size_t)z * (CC * CC / 2),
                   g_bWil + (size_t)z * (CC * CC / 2),
                   bin + z * CC, Cz, alpha);
}

__global__ void __launch_bounds__(256, 2) outproj_mma(
    const float* __restrict__ bout, float* __restrict__ out) {
    gemm_bf16_body(g_bAh, g_bAl, g_bWoh, g_bWol, bout, out, 1.0f);
}

// ---------------------------------------------------------------------------
// Gather attention (unchanged — L2-traffic-bound at algorithmic floor).
// Output written as split bf16 (hi/lo) feeding the HMMA output projection.
// ---------------------------------------------------------------------------
__global__ void __launch_bounds__(128) attn_kernel(
    const int* __restrict__ index_pair,
    const int* __restrict__ index_pair_batch,
    float* __restrict__ aux_out)
{
    __shared__ __align__(16) float sq[CC];
    __shared__ float sw[LL * HH];
    __shared__ int   sg[LL];

    const int n = blockIdx.x;
    const int t = threadIdx.x;
    const int warp = t >> 5;
    const int lane = t & 31;

    *reinterpret_cast<float4*>(&sq[t * 4]) =
        *reinterpret_cast<const float4*>(&g_q[(size_t)n * CC + t * 4]);

    if (t < LL) {
        int raw = index_pair[n * LL + t];
        int b   = index_pair_batch[n];
        sg[t] = (raw >= 0) ? (raw + g_key_start[b]) : -1;
    }
    __syncthreads();

    const float4* sq4 = reinterpret_cast<const float4*>(sq);
#pragma unroll 1
    for (int li = 0; li < 16; li++) {
        int l = warp * 16 + li;
        int g = sg[l];
        if (g < 0) {
            if (lane < 8) sw[l * 8 + lane] = -1000.0f;
            continue;
        }
        const float4* kr = reinterpret_cast<const float4*>(&g_k[(size_t)g * CC]);
#pragma unroll
        for (int p = 0; p < 4; p++) {
            float4 kv = kr[p * 32 + lane];
            float4 q4 = sq4[p * 32 + lane];
            float s = kv.x * q4.x + kv.y * q4.y + kv.z * q4.z + kv.w * q4.w;
            s += __shfl_xor_sync(0xffffffffu, s, 1);
            s += __shfl_xor_sync(0xffffffffu, s, 2);
            s += __shfl_xor_sync(0xffffffffu, s, 4);
            s += __shfl_xor_sync(0xffffffffu, s, 8);
            if ((lane & 15) == 0)
                sw[l * 8 + 2 * p + (lane >> 4)] = s;
        }
    }
    __syncthreads();

    {
        int h = t >> 4, j = t & 15;
        float vals[4];
        float m = -1e30f;
#pragma unroll
        for (int i = 0; i < 4; i++) {
            vals[i] = sw[(j + 16 * i) * 8 + h];
            m = fmaxf(m, vals[i]);
        }
#pragma unroll
        for (int off = 8; off; off >>= 1)
            m = fmaxf(m, __shfl_xor_sync(0xffffffffu, m, off, 16));
        float s = 0.0f;
#pragma unroll
        for (int i = 0; i < 4; i++) { vals[i] = expf(vals[i] - m); s += vals[i]; }
#pragma unroll
        for (int off = 8; off; off >>= 1)
            s += __shfl_xor_sync(0xffffffffu, s, off, 16);
        float inv = 1.0f / s;
#pragma unroll
        for (int i = 0; i < 4; i++)
            sw[(j + 16 * i) * 8 + h] = vals[i] * inv;
    }
    __syncthreads();

    if (t < LL) {
        float s = 0.0f;
#pragma unroll
        for (int h = 0; h < 8; h++) s += sw[t * 8 + h];
        aux_out[(size_t)n * LL + t] = s * 0.125f;
    }

    {
        int h  = t >> 4;
        int d4 = t & 15;
        float4 acc = make_float4(0.f, 0.f, 0.f, 0.f);
        size_t coloff = (size_t)(h * DD + d4 * 4);
#pragma unroll 4
        for (int l = 0; l < LL; l++) {
            int g = sg[l];
            int gg = (g >= 0) ? g : 0;
            float wgt = sw[l * 8 + h];
            float4 v4 = *reinterpret_cast<const float4*>(&g_v[(size_t)gg * CC + coloff]);
            acc.x = fmaf(wgt, v4.x, acc.x);
            acc.y = fmaf(wgt, v4.y, acc.y);
            acc.z = fmaf(wgt, v4.z, acc.z);
            acc.w = fmaf(wgt, v4.w, acc.w);
        }
        uint32_t h0 = packbf(acc.x, acc.y);
        uint32_t h1 = packbf(acc.z, acc.w);
        uint32_t l0 = packbf(acc.x - bflo(h0), acc.y - bfhi(h0));
        uint32_t l1 = packbf(acc.z - bflo(h1), acc.w - bfhi(h1));
        size_t o2 = ((size_t)n * CC + coloff) >> 1;
        *reinterpret_cast<uint2*>(&g_bAh[o2]) = make_uint2(h0, h1);
        *reinterpret_cast<uint2*>(&g_bAl[o2]) = make_uint2(l0, l1);
    }
}

// ---------------------------------------------------------------------------
extern "C" void kernel_launch(void* const* d_in, const int* in_sizes, int n_in,
                              void* d_out, int out_size) {
    const float* query  = (const float*)d_in[0];
    const float* key    = (const float*)d_in[1];
    const float* value  = (const float*)d_in[2];
    const float* Win    = (const float*)d_in[3];
    const float* bin    = (const float*)d_in[4];
    const float* Wout   = (const float*)d_in[5];
    const float* bout   = (const float*)d_in[6];
    const int*   index_pair       = (const int*)d_in[7];
    const int*   key_batch_cnt    = (const int*)d_in[9];
    const int*   index_pair_batch = (const int*)d_in[10];
    float* out = (float*)d_out;

    float* auxs;
    cudaGetSymbolAddress((void**)&auxs, g_aux_scratch);
    float* aux_out = (out_size >= NQ * CC + NQ * LL) ? (out + (size_t)NQ * CC) : auxs;

    uint32_t *bWih, *bWil, *bWoh, *bWol;
    cudaGetSymbolAddress((void**)&bWih, g_bWih); cudaGetSymbolAddress((void**)&bWil, g_bWil);
    cudaGetSymbolAddress((void**)&bWoh, g_bWoh); cudaGetSymbolAddress((void**)&bWol, g_bWol);

    cudaFuncSetAttribute(proj3_mma,   cudaFuncAttributeMaxDynamicSharedMemorySize, DSMEM_SIZE);
    cudaFuncSetAttribute(outproj_mma, cudaFuncAttributeMaxDynamicSharedMemorySize, DSMEM_SIZE);

    key_start_kernel<<<1, 32>>>(key_batch_cnt);

    // fp32 -> split-bf16 conversions
    dim3 gcvt(NQ * CC / 4 / 256, 3);
    cvt3_kernel<<<gcvt, 256>>>((const float4*)query, (const float4*)key,
                               (const float4*)value);
    cvt_split_kernel<<<3 * CC * CC / 4 / 256, 256>>>(
        (const float4*)Win, (uint2*)bWih, (uint2*)bWil, 3 * CC * CC / 4);
    cvt_split_kernel<<<CC * CC / 4 / 256, 256>>>(
        (const float4*)Wout, (uint2*)bWoh, (uint2*)bWol, CC * CC / 4);

    dim3 gproj(CC / 128, NQ / 128, 3);
    proj3_mma<<<gproj, 256, DSMEM_SIZE>>>(bin);

    attn_kernel<<<NQ, 128>>>(index_pair, index_pair_batch, aux_out);

    dim3 gout(CC / 128, NQ / 128);
    outproj_mma<<<gout, 256, DSMEM_SIZE>>>(bout, out);
}